// round 14
// baseline (speedup 1.0000x reference)
#include <cuda_runtime.h>
#include <cuda_fp16.h>
#include <cstdint>

#define DEVI static __device__ __forceinline__

// ---------------- problem dims ----------------
constexpr int Bb = 16, Nq = 1024, Cc = 1024, Hh = 16, Dd = 64, Pp = 16;
constexpr int Ll = Pp + Nq;       // 1040 keys
constexpr int Mr = Bb * Nq;       // 16384 token rows

// ---------------- scratch (device globals; no allocs allowed) ----------------
__device__ __half g_xh[Mr * Cc];            // x in fp16
__device__ __half g_wqkvh[Cc * 3 * Cc];     // w_qkv fp16 [k][n]
__device__ __half g_wprojh[Cc * Cc];        // w_proj fp16 [k][n]
__device__ __half g_Q[Bb * Hh * Nq * Dd];   // [bh][n][d], pre-scaled 0.125*log2e
__device__ __half g_K[Bb * Hh * Ll * Dd];   // [bh][p+n][d]
__device__ __half g_V[Bb * Hh * Ll * Dd];   // [bh][p+n][d]
__device__ __half g_AO[Mr * Cc];            // attention out [b*N+n][h*64+d]

// ---------------- small helpers ----------------
DEVI void cp16(void* smem, const void* gmem) {
    uint32_t s = (uint32_t)__cvta_generic_to_shared(smem);
    asm volatile("cp.async.cg.shared.global [%0], [%1], 16;\n" :: "r"(s), "l"(gmem));
}
DEVI void cp_commit() { asm volatile("cp.async.commit_group;\n"); }
template <int n> DEVI void cp_wait() { asm volatile("cp.async.wait_group %0;\n" :: "n"(n)); }

DEVI float ex2(float x) {            // 2^x via MUFU.EX2
    float r;
    asm("ex2.approx.f32 %0, %1;\n" : "=f"(r) : "f"(x));
    return r;
}

DEVI void mma16816(float* c, uint32_t a0, uint32_t a1, uint32_t a2, uint32_t a3,
                   uint32_t b0, uint32_t b1) {
    asm volatile(
        "mma.sync.aligned.m16n8k16.row.col.f32.f16.f16.f32 "
        "{%0,%1,%2,%3},{%4,%5,%6,%7},{%8,%9},{%0,%1,%2,%3};\n"
        : "+f"(c[0]), "+f"(c[1]), "+f"(c[2]), "+f"(c[3])
        : "r"(a0), "r"(a1), "r"(a2), "r"(a3), "r"(b0), "r"(b1));
}

DEVI void ldsm4(uint32_t& r0, uint32_t& r1, uint32_t& r2, uint32_t& r3, uint32_t a) {
    asm volatile("ldmatrix.sync.aligned.m8n8.x4.shared.b16 {%0,%1,%2,%3},[%4];\n"
                 : "=r"(r0), "=r"(r1), "=r"(r2), "=r"(r3) : "r"(a));
}
DEVI void ldsm4t(uint32_t& r0, uint32_t& r1, uint32_t& r2, uint32_t& r3, uint32_t a) {
    asm volatile("ldmatrix.sync.aligned.m8n8.x4.trans.shared.b16 {%0,%1,%2,%3},[%4];\n"
                 : "=r"(r0), "=r"(r1), "=r"(r2), "=r"(r3) : "r"(a));
}

DEVI uint32_t pack2(float x, float y) {
    __half2 h = __floats2half2_rn(x, y);
    return *reinterpret_cast<uint32_t*>(&h);
}
DEVI float qmax(float v) {
    v = fmaxf(v, __shfl_xor_sync(0xffffffffu, v, 1));
    v = fmaxf(v, __shfl_xor_sync(0xffffffffu, v, 2));
    return v;
}
DEVI float qsum(float v) {
    v += __shfl_xor_sync(0xffffffffu, v, 1);
    v += __shfl_xor_sync(0xffffffffu, v, 2);
    return v;
}

// ---------------- fp32 -> fp16 conversion (x, w_qkv, w_proj in one pass) ----
constexpr int NX4 = (Mr * Cc) / 4;
constexpr int NQ4 = (Cc * 3 * Cc) / 4;
constexpr int NP4 = (Cc * Cc) / 4;

__global__ void convert_all(const float* __restrict__ x,
                            const float* __restrict__ wq,
                            const float* __restrict__ wp) {
    int i = blockIdx.x * blockDim.x + threadIdx.x;
    const float4* src;
    __half2* dst;
    int j;
    if (i < NX4)            { src = (const float4*)x;  dst = (__half2*)g_xh;     j = i; }
    else if (i < NX4 + NQ4) { src = (const float4*)wq; dst = (__half2*)g_wqkvh;  j = i - NX4; }
    else if (i < NX4 + NQ4 + NP4) { src = (const float4*)wp; dst = (__half2*)g_wprojh; j = i - NX4 - NQ4; }
    else return;
    float4 v = src[j];
    dst[2 * j]     = __floats2half2_rn(v.x, v.y);
    dst[2 * j + 1] = __floats2half2_rn(v.z, v.w);
}

// ---------------- scatter prefix pk/pv into K/V heads ----------------
__global__ void prefix_kernel(const float* __restrict__ pk, const float* __restrict__ pv) {
    int i = blockIdx.x * blockDim.x + threadIdx.x;
    if (i >= Bb * Pp * Cc) return;
    int c = i & (Cc - 1);
    int bp = i >> 10;
    int p = bp & (Pp - 1);
    int b = bp >> 4;
    int h = c >> 6, d = c & 63;
    int o = ((b * Hh + h) * Ll + p) * Dd + d;
    g_K[o] = __float2half(pk[i]);
    g_V[o] = __float2half(pv[i]);
}

// ---------------- QKV scatter epilogue ----------------
constexpr float QSCALE = 0.18033688011112042f;   // 0.125 * log2(e)

DEVI void qkv_store(int m, int col, float v0, float v1) {
    int b = m >> 10, n = m & 1023;
    int s = col >> 10, cc = col & 1023;
    int h = cc >> 6, d = cc & 63;
    if (s == 0) {
        __half2 hv = __floats2half2_rn(v0 * QSCALE, v1 * QSCALE);
        *(__half2*)(g_Q + (((size_t)(b * Hh + h)) * Nq + n) * Dd + d) = hv;
    } else {
        __half2 hv = __floats2half2_rn(v0, v1);
        __half* base = (s == 1) ? g_K : g_V;
        *(__half2*)(base + (((size_t)(b * Hh + h)) * Ll + Pp + n) * Dd + d) = hv;
    }
}

// ---------------- tiled GEMM: 128x128x64, 8 warps (64x32 each), 2 stages ----
constexpr int GA_ELE = 128 * 72;                   // 9216 halves
constexpr int GB_ELE = 64 * 136;                   // 8704 halves
constexpr int GSTG_ELE = GA_ELE + GB_ELE;          // 17920
constexpr int GSMEM_BYTES = 2 * GSTG_ELE * 2;      // 71680

template <int EPI>
__global__ __launch_bounds__(256) void gemm_kernel(float* __restrict__ outp,
                                                   const float* __restrict__ bias) {
    extern __shared__ __half sm[];
    const __half* __restrict__ A  = (EPI == 0) ? g_xh : g_AO;
    const __half* __restrict__ Bm = (EPI == 0) ? g_wqkvh : g_wprojh;
    const int Nc = (EPI == 0) ? 3 * Cc : Cc;
    const int K  = Cc;

    const int tid = threadIdx.x;
    const int wid = tid >> 5, lane = tid & 31;
    const int g = lane >> 2, t = lane & 3;
    const int wm = wid >> 2, wn = wid & 3;
    const int mBase = blockIdx.y * 128, nBase = blockIdx.x * 128;

    float acc[4][4][4];
#pragma unroll
    for (int i = 0; i < 4; i++)
#pragma unroll
        for (int j = 0; j < 4; j++)
#pragma unroll
            for (int r = 0; r < 4; r++) acc[i][j][r] = 0.f;

    auto prefetch = [&](int kt, int buf) {
        __half* As = sm + buf * GSTG_ELE;
        __half* Bs = As + GA_ELE;
#pragma unroll
        for (int j = 0; j < 4; j++) {
            int ci = tid + j * 256;
            int row = ci >> 3, cc = ci & 7;
            cp16(&As[row * 72 + cc * 8],
                 A + (size_t)(mBase + row) * K + kt * 64 + cc * 8);
        }
#pragma unroll
        for (int j = 0; j < 4; j++) {
            int ci = tid + j * 256;
            int row = ci >> 4, cc = ci & 15;
            cp16(&Bs[row * 136 + cc * 8],
                 Bm + (size_t)(kt * 64 + row) * Nc + nBase + cc * 8);
        }
    };

    const int lr = lane & 15, lc = (lane >> 4) & 1;
    const int nk = K >> 6;   // 16 k-tiles

    prefetch(0, 0);
    cp_commit();
    for (int kt = 0; kt < nk; kt++) {
        if (kt + 1 < nk) { prefetch(kt + 1, (kt + 1) & 1); cp_commit(); cp_wait<1>(); }
        else             { cp_wait<0>(); }
        __syncthreads();
        const __half* As = sm + (kt & 1) * GSTG_ELE;
        const __half* Bs = As + GA_ELE;
        uint32_t abase = (uint32_t)__cvta_generic_to_shared(As)
                       + (wm * 64 + lr) * 144 + lc * 16;
        uint32_t bbase = (uint32_t)__cvta_generic_to_shared(Bs)
                       + lr * 272 + wn * 64 + lc * 16;
#pragma unroll
        for (int ks = 0; ks < 4; ks++) {
            uint32_t af[4][4];
#pragma unroll
            for (int mi = 0; mi < 4; mi++)
                ldsm4(af[mi][0], af[mi][1], af[mi][2], af[mi][3],
                      abase + mi * 16 * 144 + ks * 32);
            uint32_t bf[2][4];
#pragma unroll
            for (int nc = 0; nc < 2; nc++)
                ldsm4t(bf[nc][0], bf[nc][1], bf[nc][2], bf[nc][3],
                       bbase + ks * 16 * 272 + nc * 32);
#pragma unroll
            for (int ni = 0; ni < 4; ni++) {
                uint32_t b0 = bf[ni >> 1][(ni & 1) * 2];
                uint32_t b1 = bf[ni >> 1][(ni & 1) * 2 + 1];
#pragma unroll
                for (int mi = 0; mi < 4; mi++)
                    mma16816(acc[mi][ni], af[mi][0], af[mi][1], af[mi][2], af[mi][3], b0, b1);
            }
        }
        __syncthreads();
    }

    // epilogue
#pragma unroll
    for (int mi = 0; mi < 4; mi++) {
#pragma unroll
        for (int ni = 0; ni < 4; ni++) {
            int m = mBase + wm * 64 + mi * 16 + g;
            int col = nBase + wn * 32 + ni * 8 + 2 * t;
            if (EPI == 0) {
                qkv_store(m,     col, acc[mi][ni][0], acc[mi][ni][1]);
                qkv_store(m + 8, col, acc[mi][ni][2], acc[mi][ni][3]);
            } else {
                float b0v = bias[col], b1v = bias[col + 1];
                *(float2*)(outp + (size_t)m * Nc + col) =
                    make_float2(acc[mi][ni][0] + b0v, acc[mi][ni][1] + b1v);
                *(float2*)(outp + (size_t)(m + 8) * Nc + col) =
                    make_float2(acc[mi][ni][2] + b0v, acc[mi][ni][3] + b1v);
            }
        }
    }
}

// ---------------- flash attention: chunk-level software pipeline ------------
// Per iteration: softmax(S_ch) -> pa; QK(ch+1) -> other S buffer (independent
// of the softmax latency chain, so its mmas fill the tensor-idle window);
// PV(ch) with pa. Ping-pong sA/sB via unroll-by-2. 4-deep cp.async KV ring;
// cp_wait<1> at top guarantees chunk ch+1 resident for the early QK.
constexpr int FBUF_ELE = 2 * 64 * 72;
constexpr int FSMEM_BYTES = 4 * FBUF_ELE * 2;   // 73728

__global__ __launch_bounds__(256) void flash_kernel() {
    extern __shared__ __half fsm[];

    const int tid = threadIdx.x;
    const int wid = tid >> 5, lane = tid & 31;
    const int g = lane >> 2, t = lane & 3;
    const int lr = lane & 15, lc = (lane >> 4) & 1;
    const int bh = blockIdx.y;
    const int b = bh >> 4, h = bh & 15;
    const int m0 = blockIdx.x * 128 + wid * 16;

    const __half* __restrict__ Qb = g_Q + (size_t)bh * Nq * Dd;
    const __half* __restrict__ Kb = g_K + (size_t)bh * Ll * Dd;
    const __half* __restrict__ Vb = g_V + (size_t)bh * Ll * Dd;

    uint32_t qa[4][4];
#pragma unroll
    for (int ks = 0; ks < 4; ks++) {
        const __half* qp = Qb + (size_t)(m0 + g) * Dd + ks * 16 + 2 * t;
        qa[ks][0] = *(const uint32_t*)qp;
        qa[ks][1] = *(const uint32_t*)(qp + 8 * Dd);
        qa[ks][2] = *(const uint32_t*)(qp + 8);
        qa[ks][3] = *(const uint32_t*)(qp + 8 * Dd + 8);
    }

    float mrow[2] = {-1e30f, -1e30f};
    float lrow[2] = {0.f, 0.f};
    float o[8][4];
#pragma unroll
    for (int i = 0; i < 8; i++)
#pragma unroll
        for (int r = 0; r < 4; r++) o[i][r] = 0.f;

    auto prefetch = [&](int ch) {
        __half* Ks = fsm + (ch & 3) * FBUF_ELE;
        __half* Vs = Ks + 64 * 72;
        int kb = ch * 64;
#pragma unroll
        for (int i = 0; i < 2; i++) {
            int idx = tid + i * 256;
            int row = idx >> 3, cc = idx & 7;
            if (kb + row < Ll) {
                cp16(&Ks[row * 72 + cc * 8], Kb + (size_t)(kb + row) * Dd + cc * 8);
                cp16(&Vs[row * 72 + cc * 8], Vb + (size_t)(kb + row) * Dd + cc * 8);
            }
        }
    };

    // S = QK^T for one 64-key chunk into s (16 x 64 per warp)
    auto qk = [&](int ch, float (&s)[8][4]) {
        uint32_t kbase = (uint32_t)__cvta_generic_to_shared(fsm + (ch & 3) * FBUF_ELE)
                       + lr * 144 + lc * 16;
#pragma unroll
        for (int i = 0; i < 8; i++)
#pragma unroll
            for (int r = 0; r < 4; r++) s[i][r] = 0.f;
#pragma unroll
        for (int ntp = 0; ntp < 4; ntp++) {
#pragma unroll
            for (int ks = 0; ks < 4; ks++) {
                uint32_t r0, r1, r2, r3;
                ldsm4(r0, r1, r2, r3, kbase + ntp * 16 * 144 + ks * 32);
                mma16816(s[2 * ntp],     qa[ks][0], qa[ks][1], qa[ks][2], qa[ks][3], r0, r2);
                mma16816(s[2 * ntp + 1], qa[ks][0], qa[ks][1], qa[ks][2], qa[ks][3], r1, r3);
            }
        }
    };

    const int nch = (Ll + 63) >> 6;   // 17

    // iteration body: softmax + PV on chunk ch (scores in scur); QK(ch+1) -> snxt
    auto body = [&](int ch, float (&scur)[8][4], float (&snxt)[8][4]) {
        cp_wait<1>();                 // chunks <= ch+1 resident
        __syncthreads();              // all warps done with chunk ch-1
        if (ch + 3 < nch) prefetch(ch + 3);   // writes buf (ch-1)&3: safe after sync
        cp_commit();

        const int kc = min(64, Ll - ch * 64);
        if (kc < 64) {
#pragma unroll
            for (int nt = 0; nt < 8; nt++) {
                int c0 = nt * 8 + 2 * t;
                if (c0 >= kc)     { scur[nt][0] = -1e30f; scur[nt][2] = -1e30f; }
                if (c0 + 1 >= kc) { scur[nt][1] = -1e30f; scur[nt][3] = -1e30f; }
            }
        }
        // online softmax (base-2)
        float mx0 = -1e30f, mx1 = -1e30f;
#pragma unroll
        for (int nt = 0; nt < 8; nt++) {
            mx0 = fmaxf(mx0, fmaxf(scur[nt][0], scur[nt][1]));
            mx1 = fmaxf(mx1, fmaxf(scur[nt][2], scur[nt][3]));
        }
        mx0 = qmax(mx0); mx1 = qmax(mx1);
        float mn0 = fmaxf(mrow[0], mx0), mn1 = fmaxf(mrow[1], mx1);
        float a0 = ex2(mrow[0] - mn0), a1 = ex2(mrow[1] - mn1);
        mrow[0] = mn0; mrow[1] = mn1;
        float sum0 = 0.f, sum1 = 0.f;
#pragma unroll
        for (int nt = 0; nt < 8; nt++) {
            scur[nt][0] = ex2(scur[nt][0] - mn0);
            scur[nt][1] = ex2(scur[nt][1] - mn0);
            scur[nt][2] = ex2(scur[nt][2] - mn1);
            scur[nt][3] = ex2(scur[nt][3] - mn1);
            sum0 += scur[nt][0] + scur[nt][1];
            sum1 += scur[nt][2] + scur[nt][3];
        }
        sum0 = qsum(sum0); sum1 = qsum(sum1);
        lrow[0] = lrow[0] * a0 + sum0;
        lrow[1] = lrow[1] * a1 + sum1;
        // pack P fragments (S acc layout == A operand layout)
        uint32_t pa[4][4];
#pragma unroll
        for (int j = 0; j < 4; j++) {
            pa[j][0] = pack2(scur[2 * j][0],     scur[2 * j][1]);
            pa[j][1] = pack2(scur[2 * j][2],     scur[2 * j][3]);
            pa[j][2] = pack2(scur[2 * j + 1][0], scur[2 * j + 1][1]);
            pa[j][3] = pack2(scur[2 * j + 1][2], scur[2 * j + 1][3]);
        }
        // independent tensor work: next chunk's QK (fills softmax latency)
        if (ch + 1 < nch) qk(ch + 1, snxt);
        // rescale O, then accumulate PV(ch)
#pragma unroll
        for (int nt = 0; nt < 8; nt++) {
            o[nt][0] *= a0; o[nt][1] *= a0; o[nt][2] *= a1; o[nt][3] *= a1;
        }
        uint32_t vbase = (uint32_t)__cvta_generic_to_shared(fsm + (ch & 3) * FBUF_ELE)
                       + 64 * 144 + lr * 144 + lc * 16;
#pragma unroll
        for (int j = 0; j < 4; j++) {
#pragma unroll
            for (int dg = 0; dg < 4; dg++) {
                uint32_t v0, v1, v2, v3;
                ldsm4t(v0, v1, v2, v3, vbase + j * 16 * 144 + dg * 32);
                mma16816(o[2 * dg],     pa[j][0], pa[j][1], pa[j][2], pa[j][3], v0, v1);
                mma16816(o[2 * dg + 1], pa[j][0], pa[j][1], pa[j][2], pa[j][3], v2, v3);
            }
        }
    };

    float sA[8][4], sB[8][4];
    prefetch(0); cp_commit();
    prefetch(1); cp_commit();
    prefetch(2); cp_commit();
    cp_wait<2>();                     // chunk 0 resident
    __syncthreads();
    qk(0, sA);                        // S(0)

    for (int ch = 0; ch < nch; ch += 2) {
        body(ch, sA, sB);
        if (ch + 1 < nch) body(ch + 1, sB, sA);
    }

    // normalize + store to AO [b*N+n][h*64+d] (fp16)
    float inv0 = 1.f / lrow[0], inv1 = 1.f / lrow[1];
    size_t ro0 = ((size_t)b * Nq + (m0 + g)) * Cc + h * 64;
    size_t ro1 = ro0 + (size_t)8 * Cc;
#pragma unroll
    for (int nt = 0; nt < 8; nt++) {
        int c = nt * 8 + 2 * t;
        *(__half2*)(g_AO + ro0 + c) = __floats2half2_rn(o[nt][0] * inv0, o[nt][1] * inv0);
        *(__half2*)(g_AO + ro1 + c) = __floats2half2_rn(o[nt][2] * inv1, o[nt][3] * inv1);
    }
}

// ---------------- launch ----------------
extern "C" void kernel_launch(void* const* d_in, const int* in_sizes, int n_in,
                              void* d_out, int out_size) {
    const float* x  = (const float*)d_in[0];
    const float* pk = (const float*)d_in[1];
    const float* pv = (const float*)d_in[2];
    const float* wq = (const float*)d_in[3];
    const float* wp = (const float*)d_in[4];
    const float* bp = (const float*)d_in[5];
    float* out = (float*)d_out;

    (void)in_sizes; (void)n_in; (void)out_size;

    static bool attr_set = false;
    if (!attr_set) {
        cudaFuncSetAttribute(gemm_kernel<0>, cudaFuncAttributeMaxDynamicSharedMemorySize, GSMEM_BYTES);
        cudaFuncSetAttribute(gemm_kernel<1>, cudaFuncAttributeMaxDynamicSharedMemorySize, GSMEM_BYTES);
        cudaFuncSetAttribute(flash_kernel,   cudaFuncAttributeMaxDynamicSharedMemorySize, FSMEM_BYTES);
        attr_set = true;
    }

    int totq = NX4 + NQ4 + NP4;
    convert_all<<<(totq + 255) / 256, 256>>>(x, wq, wp);
    prefix_kernel<<<(Bb * Pp * Cc + 255) / 256, 256>>>(pk, pv);
    {
        dim3 grid(3 * Cc / 128, Mr / 128);        // (24, 128)
        gemm_kernel<0><<<grid, 256, GSMEM_BYTES>>>(nullptr, nullptr);
    }
    {
        dim3 grid(Nq / 128, Bb * Hh);             // (8, 256)
        flash_kernel<<<grid, 256, FSMEM_BYTES>>>();
    }
    {
        dim3 grid(Cc / 128, Mr / 128);            // (8, 128)
        gemm_kernel<1><<<grid, 256, GSMEM_BYTES>>>(out, bp);
    }
}

// round 15
// speedup vs baseline: 1.1387x; 1.1387x over previous
#include <cuda_runtime.h>
#include <cuda_fp16.h>
#include <cstdint>

#define DEVI static __device__ __forceinline__

// ---------------- problem dims ----------------
constexpr int Bb = 16, Nq = 1024, Cc = 1024, Hh = 16, Dd = 64, Pp = 16;
constexpr int Ll = Pp + Nq;       // 1040 keys
constexpr int Mr = Bb * Nq;       // 16384 token rows

// ---------------- scratch (device globals; no allocs allowed) ----------------
__device__ __half g_xh[Mr * Cc];            // x in fp16
__device__ __half g_wqkvh[Cc * 3 * Cc];     // w_qkv fp16 [k][n]
__device__ __half g_wprojh[Cc * Cc];        // w_proj fp16 [k][n]
__device__ __half g_Q[Bb * Hh * Nq * Dd];   // [bh][n][d], pre-scaled 0.125*log2e
__device__ __half g_K[Bb * Hh * Ll * Dd];   // [bh][p+n][d]
__device__ __half g_V[Bb * Hh * Ll * Dd];   // [bh][p+n][d]
__device__ __half g_AO[Mr * Cc];            // attention out [b*N+n][h*64+d]

// ---------------- small helpers ----------------
DEVI void cp16(void* smem, const void* gmem) {
    uint32_t s = (uint32_t)__cvta_generic_to_shared(smem);
    asm volatile("cp.async.cg.shared.global [%0], [%1], 16;\n" :: "r"(s), "l"(gmem));
}
DEVI void cp_commit() { asm volatile("cp.async.commit_group;\n"); }
template <int n> DEVI void cp_wait() { asm volatile("cp.async.wait_group %0;\n" :: "n"(n)); }

DEVI float ex2(float x) {            // 2^x via MUFU.EX2
    float r;
    asm("ex2.approx.f32 %0, %1;\n" : "=f"(r) : "f"(x));
    return r;
}

DEVI void mma16816(float* c, uint32_t a0, uint32_t a1, uint32_t a2, uint32_t a3,
                   uint32_t b0, uint32_t b1) {
    asm volatile(
        "mma.sync.aligned.m16n8k16.row.col.f32.f16.f16.f32 "
        "{%0,%1,%2,%3},{%4,%5,%6,%7},{%8,%9},{%0,%1,%2,%3};\n"
        : "+f"(c[0]), "+f"(c[1]), "+f"(c[2]), "+f"(c[3])
        : "r"(a0), "r"(a1), "r"(a2), "r"(a3), "r"(b0), "r"(b1));
}

DEVI void ldsm4(uint32_t& r0, uint32_t& r1, uint32_t& r2, uint32_t& r3, uint32_t a) {
    asm volatile("ldmatrix.sync.aligned.m8n8.x4.shared.b16 {%0,%1,%2,%3},[%4];\n"
                 : "=r"(r0), "=r"(r1), "=r"(r2), "=r"(r3) : "r"(a));
}
DEVI void ldsm4t(uint32_t& r0, uint32_t& r1, uint32_t& r2, uint32_t& r3, uint32_t a) {
    asm volatile("ldmatrix.sync.aligned.m8n8.x4.trans.shared.b16 {%0,%1,%2,%3},[%4];\n"
                 : "=r"(r0), "=r"(r1), "=r"(r2), "=r"(r3) : "r"(a));
}

DEVI uint32_t pack2(float x, float y) {
    __half2 h = __floats2half2_rn(x, y);
    return *reinterpret_cast<uint32_t*>(&h);
}
DEVI float qmax(float v) {
    v = fmaxf(v, __shfl_xor_sync(0xffffffffu, v, 1));
    v = fmaxf(v, __shfl_xor_sync(0xffffffffu, v, 2));
    return v;
}
DEVI float qsum(float v) {
    v += __shfl_xor_sync(0xffffffffu, v, 1);
    v += __shfl_xor_sync(0xffffffffu, v, 2);
    return v;
}

// ---------------- fp32 -> fp16 conversion (x, w_qkv, w_proj in one pass) ----
constexpr int NX4 = (Mr * Cc) / 4;
constexpr int NQ4 = (Cc * 3 * Cc) / 4;
constexpr int NP4 = (Cc * Cc) / 4;

__global__ void convert_all(const float* __restrict__ x,
                            const float* __restrict__ wq,
                            const float* __restrict__ wp) {
    int i = blockIdx.x * blockDim.x + threadIdx.x;
    const float4* src;
    __half2* dst;
    int j;
    if (i < NX4)            { src = (const float4*)x;  dst = (__half2*)g_xh;     j = i; }
    else if (i < NX4 + NQ4) { src = (const float4*)wq; dst = (__half2*)g_wqkvh;  j = i - NX4; }
    else if (i < NX4 + NQ4 + NP4) { src = (const float4*)wp; dst = (__half2*)g_wprojh; j = i - NX4 - NQ4; }
    else return;
    float4 v = src[j];
    dst[2 * j]     = __floats2half2_rn(v.x, v.y);
    dst[2 * j + 1] = __floats2half2_rn(v.z, v.w);
}

// ---------------- scatter prefix pk/pv into K/V heads ----------------
__global__ void prefix_kernel(const float* __restrict__ pk, const float* __restrict__ pv) {
    int i = blockIdx.x * blockDim.x + threadIdx.x;
    if (i >= Bb * Pp * Cc) return;
    int c = i & (Cc - 1);
    int bp = i >> 10;
    int p = bp & (Pp - 1);
    int b = bp >> 4;
    int h = c >> 6, d = c & 63;
    int o = ((b * Hh + h) * Ll + p) * Dd + d;
    g_K[o] = __float2half(pk[i]);
    g_V[o] = __float2half(pv[i]);
}

// ---------------- QKV scatter epilogue ----------------
constexpr float QSCALE = 0.18033688011112042f;   // 0.125 * log2(e)

DEVI void qkv_store(int m, int col, float v0, float v1) {
    int b = m >> 10, n = m & 1023;
    int s = col >> 10, cc = col & 1023;
    int h = cc >> 6, d = cc & 63;
    if (s == 0) {
        __half2 hv = __floats2half2_rn(v0 * QSCALE, v1 * QSCALE);
        *(__half2*)(g_Q + (((size_t)(b * Hh + h)) * Nq + n) * Dd + d) = hv;
    } else {
        __half2 hv = __floats2half2_rn(v0, v1);
        __half* base = (s == 1) ? g_K : g_V;
        *(__half2*)(base + (((size_t)(b * Hh + h)) * Ll + Pp + n) * Dd + d) = hv;
    }
}

// ---------------- tiled GEMM: 128x128x64, 8 warps (64x32 each), 2 stages ----
// (identical to the 696.5us best-passing version)
constexpr int GA_ELE = 128 * 72;                   // 9216 halves
constexpr int GB_ELE = 64 * 136;                   // 8704 halves
constexpr int GSTG_ELE = GA_ELE + GB_ELE;          // 17920
constexpr int GSMEM_BYTES = 2 * GSTG_ELE * 2;      // 71680

template <int EPI>
__global__ __launch_bounds__(256) void gemm_kernel(float* __restrict__ outp,
                                                   const float* __restrict__ bias) {
    extern __shared__ __half sm[];
    const __half* __restrict__ A  = (EPI == 0) ? g_xh : g_AO;
    const __half* __restrict__ Bm = (EPI == 0) ? g_wqkvh : g_wprojh;
    const int Nc = (EPI == 0) ? 3 * Cc : Cc;
    const int K  = Cc;

    const int tid = threadIdx.x;
    const int wid = tid >> 5, lane = tid & 31;
    const int g = lane >> 2, t = lane & 3;
    const int wm = wid >> 2, wn = wid & 3;
    const int mBase = blockIdx.y * 128, nBase = blockIdx.x * 128;

    float acc[4][4][4];
#pragma unroll
    for (int i = 0; i < 4; i++)
#pragma unroll
        for (int j = 0; j < 4; j++)
#pragma unroll
            for (int r = 0; r < 4; r++) acc[i][j][r] = 0.f;

    auto prefetch = [&](int kt, int buf) {
        __half* As = sm + buf * GSTG_ELE;
        __half* Bs = As + GA_ELE;
#pragma unroll
        for (int j = 0; j < 4; j++) {
            int ci = tid + j * 256;
            int row = ci >> 3, cc = ci & 7;
            cp16(&As[row * 72 + cc * 8],
                 A + (size_t)(mBase + row) * K + kt * 64 + cc * 8);
        }
#pragma unroll
        for (int j = 0; j < 4; j++) {
            int ci = tid + j * 256;
            int row = ci >> 4, cc = ci & 15;
            cp16(&Bs[row * 136 + cc * 8],
                 Bm + (size_t)(kt * 64 + row) * Nc + nBase + cc * 8);
        }
    };

    const int lr = lane & 15, lc = (lane >> 4) & 1;
    const int nk = K >> 6;   // 16 k-tiles

    prefetch(0, 0);
    cp_commit();
    for (int kt = 0; kt < nk; kt++) {
        if (kt + 1 < nk) { prefetch(kt + 1, (kt + 1) & 1); cp_commit(); cp_wait<1>(); }
        else             { cp_wait<0>(); }
        __syncthreads();
        const __half* As = sm + (kt & 1) * GSTG_ELE;
        const __half* Bs = As + GA_ELE;
        uint32_t abase = (uint32_t)__cvta_generic_to_shared(As)
                       + (wm * 64 + lr) * 144 + lc * 16;
        uint32_t bbase = (uint32_t)__cvta_generic_to_shared(Bs)
                       + lr * 272 + wn * 64 + lc * 16;
#pragma unroll
        for (int ks = 0; ks < 4; ks++) {
            uint32_t af[4][4];
#pragma unroll
            for (int mi = 0; mi < 4; mi++)
                ldsm4(af[mi][0], af[mi][1], af[mi][2], af[mi][3],
                      abase + mi * 16 * 144 + ks * 32);
            uint32_t bf[2][4];
#pragma unroll
            for (int nc = 0; nc < 2; nc++)
                ldsm4t(bf[nc][0], bf[nc][1], bf[nc][2], bf[nc][3],
                       bbase + ks * 16 * 272 + nc * 32);
#pragma unroll
            for (int ni = 0; ni < 4; ni++) {
                uint32_t b0 = bf[ni >> 1][(ni & 1) * 2];
                uint32_t b1 = bf[ni >> 1][(ni & 1) * 2 + 1];
#pragma unroll
                for (int mi = 0; mi < 4; mi++)
                    mma16816(acc[mi][ni], af[mi][0], af[mi][1], af[mi][2], af[mi][3], b0, b1);
            }
        }
        __syncthreads();
    }

    // epilogue
#pragma unroll
    for (int mi = 0; mi < 4; mi++) {
#pragma unroll
        for (int ni = 0; ni < 4; ni++) {
            int m = mBase + wm * 64 + mi * 16 + g;
            int col = nBase + wn * 32 + ni * 8 + 2 * t;
            if (EPI == 0) {
                qkv_store(m,     col, acc[mi][ni][0], acc[mi][ni][1]);
                qkv_store(m + 8, col, acc[mi][ni][2], acc[mi][ni][3]);
            } else {
                float b0v = bias[col], b1v = bias[col + 1];
                *(float2*)(outp + (size_t)m * Nc + col) =
                    make_float2(acc[mi][ni][0] + b0v, acc[mi][ni][1] + b1v);
                *(float2*)(outp + (size_t)(m + 8) * Nc + col) =
                    make_float2(acc[mi][ni][2] + b0v, acc[mi][ni][3] + b1v);
            }
        }
    }
}

// ---------------- flash attention v2: 32 q-rows/warp, 4 warps/CTA -----------
// Each K/V ldmatrix fragment now feeds 4 mmas (2 key/d tiles x 2 q-tiles)
// instead of 2 -> smem bytes/FLOP halves (0.125 -> 0.0625), lifting the
// crossbar-imposed 50% tensor ceiling to ~100%. 128 threads/CTA keeps
// 2 CTAs/SM even at ~190 regs. Flow identical to the proven R13 kernel.
constexpr int FBUF_ELE = 2 * 64 * 72;
constexpr int FSMEM_BYTES = 4 * FBUF_ELE * 2;   // 73728

__global__ __launch_bounds__(128) void flash_kernel() {
    extern __shared__ __half fsm[];

    const int tid = threadIdx.x;
    const int wid = tid >> 5, lane = tid & 31;
    const int g = lane >> 2, t = lane & 3;
    const int lr = lane & 15, lc = (lane >> 4) & 1;
    const int bh = blockIdx.y;
    const int b = bh >> 4, h = bh & 15;
    const int m0 = blockIdx.x * 128 + wid * 32;   // this warp's 32 q rows

    const __half* __restrict__ Qb = g_Q + (size_t)bh * Nq * Dd;
    const __half* __restrict__ Kb = g_K + (size_t)bh * Ll * Dd;
    const __half* __restrict__ Vb = g_V + (size_t)bh * Ll * Dd;

    // Q fragments for both 16-row tiles (pre-scaled 0.125*log2e)
    uint32_t qa[2][4][4];
#pragma unroll
    for (int qt = 0; qt < 2; qt++)
#pragma unroll
        for (int ks = 0; ks < 4; ks++) {
            const __half* qp = Qb + (size_t)(m0 + qt * 16 + g) * Dd + ks * 16 + 2 * t;
            qa[qt][ks][0] = *(const uint32_t*)qp;
            qa[qt][ks][1] = *(const uint32_t*)(qp + 8 * Dd);
            qa[qt][ks][2] = *(const uint32_t*)(qp + 8);
            qa[qt][ks][3] = *(const uint32_t*)(qp + 8 * Dd + 8);
        }

    float mrow[2][2] = {{-1e30f, -1e30f}, {-1e30f, -1e30f}};
    float lrow[2][2] = {{0.f, 0.f}, {0.f, 0.f}};
    float o[2][8][4];
#pragma unroll
    for (int qt = 0; qt < 2; qt++)
#pragma unroll
        for (int i = 0; i < 8; i++)
#pragma unroll
            for (int r = 0; r < 4; r++) o[qt][i][r] = 0.f;

    auto prefetch = [&](int ch) {
        __half* Ks = fsm + (ch & 3) * FBUF_ELE;
        __half* Vs = Ks + 64 * 72;
        int kb = ch * 64;
#pragma unroll
        for (int i = 0; i < 4; i++) {
            int idx = tid + i * 128;
            int row = idx >> 3, cc = idx & 7;
            if (kb + row < Ll) {
                cp16(&Ks[row * 72 + cc * 8], Kb + (size_t)(kb + row) * Dd + cc * 8);
                cp16(&Vs[row * 72 + cc * 8], Vb + (size_t)(kb + row) * Dd + cc * 8);
            }
        }
    };

    const int nch = (Ll + 63) >> 6;   // 17
    prefetch(0); cp_commit();
    prefetch(1); cp_commit();
    prefetch(2); cp_commit();

    for (int ch = 0; ch < nch; ch++) {
        const int kc = min(64, Ll - ch * 64);
        cp_wait<2>();
        __syncthreads();
        if (ch + 3 < nch) prefetch(ch + 3);
        cp_commit();

        uint32_t kbase = (uint32_t)__cvta_generic_to_shared(fsm + (ch & 3) * FBUF_ELE)
                       + lr * 144 + lc * 16;
        uint32_t vbase = kbase + 64 * 144;

        // S = QK^T for BOTH q-tiles; each K frag feeds 4 mmas
        float s[2][8][4];
#pragma unroll
        for (int qt = 0; qt < 2; qt++)
#pragma unroll
            for (int i = 0; i < 8; i++)
#pragma unroll
                for (int r = 0; r < 4; r++) s[qt][i][r] = 0.f;
#pragma unroll
        for (int ntp = 0; ntp < 4; ntp++) {
#pragma unroll
            for (int ks = 0; ks < 4; ks++) {
                uint32_t r0, r1, r2, r3;
                ldsm4(r0, r1, r2, r3, kbase + ntp * 16 * 144 + ks * 32);
                mma16816(s[0][2 * ntp],     qa[0][ks][0], qa[0][ks][1], qa[0][ks][2], qa[0][ks][3], r0, r2);
                mma16816(s[0][2 * ntp + 1], qa[0][ks][0], qa[0][ks][1], qa[0][ks][2], qa[0][ks][3], r1, r3);
                mma16816(s[1][2 * ntp],     qa[1][ks][0], qa[1][ks][1], qa[1][ks][2], qa[1][ks][3], r0, r2);
                mma16816(s[1][2 * ntp + 1], qa[1][ks][0], qa[1][ks][1], qa[1][ks][2], qa[1][ks][3], r1, r3);
            }
        }
        if (kc < 64) {
#pragma unroll
            for (int qt = 0; qt < 2; qt++)
#pragma unroll
                for (int nt = 0; nt < 8; nt++) {
                    int c0 = nt * 8 + 2 * t;
                    if (c0 >= kc)     { s[qt][nt][0] = -1e30f; s[qt][nt][2] = -1e30f; }
                    if (c0 + 1 >= kc) { s[qt][nt][1] = -1e30f; s[qt][nt][3] = -1e30f; }
                }
        }
        // online softmax (base-2) per q-tile; pack into pa in place
        uint32_t pa[2][4][4];
        float av[2][2];
#pragma unroll
        for (int qt = 0; qt < 2; qt++) {
            float mx0 = -1e30f, mx1 = -1e30f;
#pragma unroll
            for (int nt = 0; nt < 8; nt++) {
                mx0 = fmaxf(mx0, fmaxf(s[qt][nt][0], s[qt][nt][1]));
                mx1 = fmaxf(mx1, fmaxf(s[qt][nt][2], s[qt][nt][3]));
            }
            mx0 = qmax(mx0); mx1 = qmax(mx1);
            float mn0 = fmaxf(mrow[qt][0], mx0), mn1 = fmaxf(mrow[qt][1], mx1);
            float a0 = ex2(mrow[qt][0] - mn0), a1 = ex2(mrow[qt][1] - mn1);
            mrow[qt][0] = mn0; mrow[qt][1] = mn1;
            av[qt][0] = a0; av[qt][1] = a1;
            float sum0 = 0.f, sum1 = 0.f;
#pragma unroll
            for (int nt = 0; nt < 8; nt++) {
                s[qt][nt][0] = ex2(s[qt][nt][0] - mn0);
                s[qt][nt][1] = ex2(s[qt][nt][1] - mn0);
                s[qt][nt][2] = ex2(s[qt][nt][2] - mn1);
                s[qt][nt][3] = ex2(s[qt][nt][3] - mn1);
                sum0 += s[qt][nt][0] + s[qt][nt][1];
                sum1 += s[qt][nt][2] + s[qt][nt][3];
            }
            sum0 = qsum(sum0); sum1 = qsum(sum1);
            lrow[qt][0] = lrow[qt][0] * a0 + sum0;
            lrow[qt][1] = lrow[qt][1] * a1 + sum1;
#pragma unroll
            for (int j = 0; j < 4; j++) {
                pa[qt][j][0] = pack2(s[qt][2 * j][0],     s[qt][2 * j][1]);
                pa[qt][j][1] = pack2(s[qt][2 * j][2],     s[qt][2 * j][3]);
                pa[qt][j][2] = pack2(s[qt][2 * j + 1][0], s[qt][2 * j + 1][1]);
                pa[qt][j][3] = pack2(s[qt][2 * j + 1][2], s[qt][2 * j + 1][3]);
            }
            // rescale O
#pragma unroll
            for (int nt = 0; nt < 8; nt++) {
                o[qt][nt][0] *= a0; o[qt][nt][1] *= a0;
                o[qt][nt][2] *= a1; o[qt][nt][3] *= a1;
            }
        }
        // O += P @ V for BOTH q-tiles; each V frag feeds 4 mmas
#pragma unroll
        for (int j = 0; j < 4; j++) {
#pragma unroll
            for (int dg = 0; dg < 4; dg++) {
                uint32_t v0, v1, v2, v3;
                ldsm4t(v0, v1, v2, v3, vbase + j * 16 * 144 + dg * 32);
                mma16816(o[0][2 * dg],     pa[0][j][0], pa[0][j][1], pa[0][j][2], pa[0][j][3], v0, v1);
                mma16816(o[0][2 * dg + 1], pa[0][j][0], pa[0][j][1], pa[0][j][2], pa[0][j][3], v2, v3);
                mma16816(o[1][2 * dg],     pa[1][j][0], pa[1][j][1], pa[1][j][2], pa[1][j][3], v0, v1);
                mma16816(o[1][2 * dg + 1], pa[1][j][0], pa[1][j][1], pa[1][j][2], pa[1][j][3], v2, v3);
            }
        }
    }

    // normalize + store both q-tiles to AO [b*N+n][h*64+d] (fp16)
#pragma unroll
    for (int qt = 0; qt < 2; qt++) {
        float inv0 = 1.f / lrow[qt][0], inv1 = 1.f / lrow[qt][1];
        size_t ro0 = ((size_t)b * Nq + (m0 + qt * 16 + g)) * Cc + h * 64;
        size_t ro1 = ro0 + (size_t)8 * Cc;
#pragma unroll
        for (int nt = 0; nt < 8; nt++) {
            int c = nt * 8 + 2 * t;
            *(__half2*)(g_AO + ro0 + c) = __floats2half2_rn(o[qt][nt][0] * inv0, o[qt][nt][1] * inv0);
            *(__half2*)(g_AO + ro1 + c) = __floats2half2_rn(o[qt][nt][2] * inv1, o[qt][nt][3] * inv1);
        }
    }
}

// ---------------- launch ----------------
extern "C" void kernel_launch(void* const* d_in, const int* in_sizes, int n_in,
                              void* d_out, int out_size) {
    const float* x  = (const float*)d_in[0];
    const float* pk = (const float*)d_in[1];
    const float* pv = (const float*)d_in[2];
    const float* wq = (const float*)d_in[3];
    const float* wp = (const float*)d_in[4];
    const float* bp = (const float*)d_in[5];
    float* out = (float*)d_out;

    (void)in_sizes; (void)n_in; (void)out_size;

    static bool attr_set = false;
    if (!attr_set) {
        cudaFuncSetAttribute(gemm_kernel<0>, cudaFuncAttributeMaxDynamicSharedMemorySize, GSMEM_BYTES);
        cudaFuncSetAttribute(gemm_kernel<1>, cudaFuncAttributeMaxDynamicSharedMemorySize, GSMEM_BYTES);
        cudaFuncSetAttribute(flash_kernel,   cudaFuncAttributeMaxDynamicSharedMemorySize, FSMEM_BYTES);
        attr_set = true;
    }

    int totq = NX4 + NQ4 + NP4;
    convert_all<<<(totq + 255) / 256, 256>>>(x, wq, wp);
    prefix_kernel<<<(Bb * Pp * Cc + 255) / 256, 256>>>(pk, pv);
    {
        dim3 grid(3 * Cc / 128, Mr / 128);        // (24, 128)
        gemm_kernel<0><<<grid, 256, GSMEM_BYTES>>>(nullptr, nullptr);
    }
    {
        dim3 grid(Nq / 128, Bb * Hh);             // (8, 256) - 128 q-rows/CTA, 4 warps
        flash_kernel<<<grid, 128, FSMEM_BYTES>>>();
    }
    {
        dim3 grid(Cc / 128, Mr / 128);            // (8, 128)
        gemm_kernel<1><<<grid, 256, GSMEM_BYTES>>>(out, bp);
    }
}

// round 17
// speedup vs baseline: 1.2382x; 1.0873x over previous
#include <cuda_runtime.h>
#include <cuda_fp16.h>
#include <cstdint>

#define DEVI static __device__ __forceinline__

// ---------------- problem dims ----------------
constexpr int Bb = 16, Nq = 1024, Cc = 1024, Hh = 16, Dd = 64, Pp = 16;
constexpr int Ll = Pp + Nq;       // 1040 keys
constexpr int Mr = Bb * Nq;       // 16384 token rows

// ---------------- scratch (device globals; no allocs allowed) ----------------
__device__ __half g_xh[Mr * Cc];            // x in fp16
__device__ __half g_wqkvh[Cc * 3 * Cc];     // w_qkv fp16 [k][n]
__device__ __half g_wprojh[Cc * Cc];        // w_proj fp16 [k][n]
__device__ __half g_Q[Bb * Hh * Nq * Dd];   // [bh][n][d], pre-scaled 0.125*log2e
__device__ __half g_K[Bb * Hh * Ll * Dd];   // [bh][p+n][d]
__device__ __half g_V[Bb * Hh * Ll * Dd];   // [bh][p+n][d]
__device__ __half g_AO[Mr * Cc];            // attention out [b*N+n][h*64+d]

// ---------------- small helpers ----------------
DEVI void cp16(void* smem, const void* gmem) {
    uint32_t s = (uint32_t)__cvta_generic_to_shared(smem);
    asm volatile("cp.async.cg.shared.global [%0], [%1], 16;\n" :: "r"(s), "l"(gmem));
}
DEVI void cp_commit() { asm volatile("cp.async.commit_group;\n"); }
template <int n> DEVI void cp_wait() { asm volatile("cp.async.wait_group %0;\n" :: "n"(n)); }

DEVI float ex2(float x) {            // 2^x via MUFU.EX2
    float r;
    asm("ex2.approx.f32 %0, %1;\n" : "=f"(r) : "f"(x));
    return r;
}

DEVI void mma16816(float* c, uint32_t a0, uint32_t a1, uint32_t a2, uint32_t a3,
                   uint32_t b0, uint32_t b1) {
    asm volatile(
        "mma.sync.aligned.m16n8k16.row.col.f32.f16.f16.f32 "
        "{%0,%1,%2,%3},{%4,%5,%6,%7},{%8,%9},{%0,%1,%2,%3};\n"
        : "+f"(c[0]), "+f"(c[1]), "+f"(c[2]), "+f"(c[3])
        : "r"(a0), "r"(a1), "r"(a2), "r"(a3), "r"(b0), "r"(b1));
}

DEVI void ldsm4(uint32_t& r0, uint32_t& r1, uint32_t& r2, uint32_t& r3, uint32_t a) {
    asm volatile("ldmatrix.sync.aligned.m8n8.x4.shared.b16 {%0,%1,%2,%3},[%4];\n"
                 : "=r"(r0), "=r"(r1), "=r"(r2), "=r"(r3) : "r"(a));
}
DEVI void ldsm4t(uint32_t& r0, uint32_t& r1, uint32_t& r2, uint32_t& r3, uint32_t a) {
    asm volatile("ldmatrix.sync.aligned.m8n8.x4.trans.shared.b16 {%0,%1,%2,%3},[%4];\n"
                 : "=r"(r0), "=r"(r1), "=r"(r2), "=r"(r3) : "r"(a));
}

DEVI uint32_t pack2(float x, float y) {
    __half2 h = __floats2half2_rn(x, y);
    return *reinterpret_cast<uint32_t*>(&h);
}
DEVI float qmax(float v) {
    v = fmaxf(v, __shfl_xor_sync(0xffffffffu, v, 1));
    v = fmaxf(v, __shfl_xor_sync(0xffffffffu, v, 2));
    return v;
}
DEVI float qsum(float v) {
    v += __shfl_xor_sync(0xffffffffu, v, 1);
    v += __shfl_xor_sync(0xffffffffu, v, 2);
    return v;
}

// ---------------- fp32 -> fp16 conversion (x, w_qkv, w_proj in one pass) ----
constexpr int NX4 = (Mr * Cc) / 4;
constexpr int NQ4 = (Cc * 3 * Cc) / 4;
constexpr int NP4 = (Cc * Cc) / 4;

__global__ void convert_all(const float* __restrict__ x,
                            const float* __restrict__ wq,
                            const float* __restrict__ wp) {
    int i = blockIdx.x * blockDim.x + threadIdx.x;
    const float4* src;
    __half2* dst;
    int j;
    if (i < NX4)            { src = (const float4*)x;  dst = (__half2*)g_xh;     j = i; }
    else if (i < NX4 + NQ4) { src = (const float4*)wq; dst = (__half2*)g_wqkvh;  j = i - NX4; }
    else if (i < NX4 + NQ4 + NP4) { src = (const float4*)wp; dst = (__half2*)g_wprojh; j = i - NX4 - NQ4; }
    else return;
    float4 v = src[j];
    dst[2 * j]     = __floats2half2_rn(v.x, v.y);
    dst[2 * j + 1] = __floats2half2_rn(v.z, v.w);
}

// ---------------- scatter prefix pk/pv into K/V heads ----------------
__global__ void prefix_kernel(const float* __restrict__ pk, const float* __restrict__ pv) {
    int i = blockIdx.x * blockDim.x + threadIdx.x;
    if (i >= Bb * Pp * Cc) return;
    int c = i & (Cc - 1);
    int bp = i >> 10;
    int p = bp & (Pp - 1);
    int b = bp >> 4;
    int h = c >> 6, d = c & 63;
    int o = ((b * Hh + h) * Ll + p) * Dd + d;
    g_K[o] = __float2half(pk[i]);
    g_V[o] = __float2half(pv[i]);
}

// ---------------- QKV scatter epilogue ----------------
constexpr float QSCALE = 0.18033688011112042f;   // 0.125 * log2(e)

DEVI void qkv_store(int m, int col, float v0, float v1) {
    int b = m >> 10, n = m & 1023;
    int s = col >> 10, cc = col & 1023;
    int h = cc >> 6, d = cc & 63;
    if (s == 0) {
        __half2 hv = __floats2half2_rn(v0 * QSCALE, v1 * QSCALE);
        *(__half2*)(g_Q + (((size_t)(b * Hh + h)) * Nq + n) * Dd + d) = hv;
    } else {
        __half2 hv = __floats2half2_rn(v0, v1);
        __half* base = (s == 1) ? g_K : g_V;
        *(__half2*)(base + (((size_t)(b * Hh + h)) * Ll + Pp + n) * Dd + d) = hv;
    }
}

// ---------------- tiled GEMM v2: 128x128x64, 4 warps (64x64 each), 2 stages -
// Flash-validated operating point: 128 thr/CTA, ~200 regs, 2 CTAs/SM.
// Per ks step: 8 ldsm feed 32 mma (4:1) -> smem demand 64 B/cyc < 128 B/cyc.
constexpr int GA_ELE = 128 * 72;                   // 9216 halves
constexpr int GB_ELE = 64 * 136;                   // 8704 halves
constexpr int GSTG_ELE = GA_ELE + GB_ELE;          // 17920
constexpr int GSMEM_BYTES = 2 * GSTG_ELE * 2;      // 71680

template <int EPI>
__global__ __launch_bounds__(128) void gemm_kernel(float* __restrict__ outp,
                                                   const float* __restrict__ bias) {
    extern __shared__ __half sm[];
    const __half* __restrict__ A  = (EPI == 0) ? g_xh : g_AO;
    const __half* __restrict__ Bm = (EPI == 0) ? g_wqkvh : g_wprojh;
    const int Nc = (EPI == 0) ? 3 * Cc : Cc;
    const int K  = Cc;

    const int tid = threadIdx.x;
    const int wid = tid >> 5, lane = tid & 31;
    const int g = lane >> 2, t = lane & 3;
    const int wm = wid >> 1, wn = wid & 1;         // 2x2 warp grid, warp tile 64x64
    const int mBase = blockIdx.y * 128, nBase = blockIdx.x * 128;

    float acc[4][8][4];
#pragma unroll
    for (int i = 0; i < 4; i++)
#pragma unroll
        for (int j = 0; j < 8; j++)
#pragma unroll
            for (int r = 0; r < 4; r++) acc[i][j][r] = 0.f;

    auto prefetch = [&](int kt, int buf) {
        __half* As = sm + buf * GSTG_ELE;
        __half* Bs = As + GA_ELE;
        // A: 128 rows x 8 chunks = 1024, 8/thread
#pragma unroll
        for (int j = 0; j < 8; j++) {
            int ci = tid + j * 128;
            int row = ci >> 3, cc = ci & 7;
            cp16(&As[row * 72 + cc * 8],
                 A + (size_t)(mBase + row) * K + kt * 64 + cc * 8);
        }
        // B: 64 rows x 16 chunks = 1024, 8/thread
#pragma unroll
        for (int j = 0; j < 8; j++) {
            int ci = tid + j * 128;
            int row = ci >> 4, cc = ci & 15;
            cp16(&Bs[row * 136 + cc * 8],
                 Bm + (size_t)(kt * 64 + row) * Nc + nBase + cc * 8);
        }
    };

    const int lr = lane & 15, lc = (lane >> 4) & 1;
    const int nk = K >> 6;   // 16 k-tiles

    prefetch(0, 0);
    cp_commit();
    for (int kt = 0; kt < nk; kt++) {
        if (kt + 1 < nk) { prefetch(kt + 1, (kt + 1) & 1); cp_commit(); cp_wait<1>(); }
        else             { cp_wait<0>(); }
        __syncthreads();
        const __half* As = sm + (kt & 1) * GSTG_ELE;
        const __half* Bs = As + GA_ELE;
        uint32_t abase = (uint32_t)__cvta_generic_to_shared(As)
                       + (wm * 64 + lr) * 144 + lc * 16;
        uint32_t bbase = (uint32_t)__cvta_generic_to_shared(Bs)
                       + lr * 272 + wn * 128 + lc * 16;
#pragma unroll
        for (int ks = 0; ks < 4; ks++) {
            uint32_t af[4][4];
#pragma unroll
            for (int mi = 0; mi < 4; mi++)
                ldsm4(af[mi][0], af[mi][1], af[mi][2], af[mi][3],
                      abase + mi * 16 * 144 + ks * 32);
            uint32_t bf[4][4];
#pragma unroll
            for (int nc = 0; nc < 4; nc++)
                ldsm4t(bf[nc][0], bf[nc][1], bf[nc][2], bf[nc][3],
                       bbase + ks * 16 * 272 + nc * 32);
#pragma unroll
            for (int ni = 0; ni < 8; ni++) {
                uint32_t b0 = bf[ni >> 1][(ni & 1) * 2];
                uint32_t b1 = bf[ni >> 1][(ni & 1) * 2 + 1];
#pragma unroll
                for (int mi = 0; mi < 4; mi++)
                    mma16816(acc[mi][ni], af[mi][0], af[mi][1], af[mi][2], af[mi][3], b0, b1);
            }
        }
        __syncthreads();
    }

    // epilogue
#pragma unroll
    for (int mi = 0; mi < 4; mi++) {
#pragma unroll
        for (int ni = 0; ni < 8; ni++) {
            int m = mBase + wm * 64 + mi * 16 + g;
            int col = nBase + wn * 64 + ni * 8 + 2 * t;
            if (EPI == 0) {
                qkv_store(m,     col, acc[mi][ni][0], acc[mi][ni][1]);
                qkv_store(m + 8, col, acc[mi][ni][2], acc[mi][ni][3]);
            } else {
                float b0v = bias[col], b1v = bias[col + 1];
                *(float2*)(outp + (size_t)m * Nc + col) =
                    make_float2(acc[mi][ni][0] + b0v, acc[mi][ni][1] + b1v);
                *(float2*)(outp + (size_t)(m + 8) * Nc + col) =
                    make_float2(acc[mi][ni][2] + b0v, acc[mi][ni][3] + b1v);
            }
        }
    }
}

// ---------------- flash attention v2 (663.7us passing version) --------------
// 32 q-rows/warp, 4 warps/CTA; each K/V ldmatrix fragment feeds 4 mmas.
constexpr int FBUF_ELE = 2 * 64 * 72;
constexpr int FSMEM_BYTES = 4 * FBUF_ELE * 2;   // 73728

__global__ __launch_bounds__(128) void flash_kernel() {
    extern __shared__ __half fsm[];

    const int tid = threadIdx.x;
    const int wid = tid >> 5, lane = tid & 31;
    const int g = lane >> 2, t = lane & 3;
    const int lr = lane & 15, lc = (lane >> 4) & 1;
    const int bh = blockIdx.y;
    const int b = bh >> 4, h = bh & 15;
    const int m0 = blockIdx.x * 128 + wid * 32;   // this warp's 32 q rows

    const __half* __restrict__ Qb = g_Q + (size_t)bh * Nq * Dd;
    const __half* __restrict__ Kb = g_K + (size_t)bh * Ll * Dd;
    const __half* __restrict__ Vb = g_V + (size_t)bh * Ll * Dd;

    // Q fragments for both 16-row tiles (pre-scaled 0.125*log2e)
    uint32_t qa[2][4][4];
#pragma unroll
    for (int qt = 0; qt < 2; qt++)
#pragma unroll
        for (int ks = 0; ks < 4; ks++) {
            const __half* qp = Qb + (size_t)(m0 + qt * 16 + g) * Dd + ks * 16 + 2 * t;
            qa[qt][ks][0] = *(const uint32_t*)qp;
            qa[qt][ks][1] = *(const uint32_t*)(qp + 8 * Dd);
            qa[qt][ks][2] = *(const uint32_t*)(qp + 8);
            qa[qt][ks][3] = *(const uint32_t*)(qp + 8 * Dd + 8);
        }

    float mrow[2][2] = {{-1e30f, -1e30f}, {-1e30f, -1e30f}};
    float lrow[2][2] = {{0.f, 0.f}, {0.f, 0.f}};
    float o[2][8][4];
#pragma unroll
    for (int qt = 0; qt < 2; qt++)
#pragma unroll
        for (int i = 0; i < 8; i++)
#pragma unroll
            for (int r = 0; r < 4; r++) o[qt][i][r] = 0.f;

    auto prefetch = [&](int ch) {
        __half* Ks = fsm + (ch & 3) * FBUF_ELE;
        __half* Vs = Ks + 64 * 72;
        int kb = ch * 64;
#pragma unroll
        for (int i = 0; i < 4; i++) {
            int idx = tid + i * 128;
            int row = idx >> 3, cc = idx & 7;
            if (kb + row < Ll) {
                cp16(&Ks[row * 72 + cc * 8], Kb + (size_t)(kb + row) * Dd + cc * 8);
                cp16(&Vs[row * 72 + cc * 8], Vb + (size_t)(kb + row) * Dd + cc * 8);
            }
        }
    };

    const int nch = (Ll + 63) >> 6;   // 17
    prefetch(0); cp_commit();
    prefetch(1); cp_commit();
    prefetch(2); cp_commit();

    for (int ch = 0; ch < nch; ch++) {
        const int kc = min(64, Ll - ch * 64);
        cp_wait<2>();
        __syncthreads();
        if (ch + 3 < nch) prefetch(ch + 3);
        cp_commit();

        uint32_t kbase = (uint32_t)__cvta_generic_to_shared(fsm + (ch & 3) * FBUF_ELE)
                       + lr * 144 + lc * 16;
        uint32_t vbase = kbase + 64 * 144;

        // S = QK^T for BOTH q-tiles; each K frag feeds 4 mmas
        float s[2][8][4];
#pragma unroll
        for (int qt = 0; qt < 2; qt++)
#pragma unroll
            for (int i = 0; i < 8; i++)
#pragma unroll
                for (int r = 0; r < 4; r++) s[qt][i][r] = 0.f;
#pragma unroll
        for (int ntp = 0; ntp < 4; ntp++) {
#pragma unroll
            for (int ks = 0; ks < 4; ks++) {
                uint32_t r0, r1, r2, r3;
                ldsm4(r0, r1, r2, r3, kbase + ntp * 16 * 144 + ks * 32);
                mma16816(s[0][2 * ntp],     qa[0][ks][0], qa[0][ks][1], qa[0][ks][2], qa[0][ks][3], r0, r2);
                mma16816(s[0][2 * ntp + 1], qa[0][ks][0], qa[0][ks][1], qa[0][ks][2], qa[0][ks][3], r1, r3);
                mma16816(s[1][2 * ntp],     qa[1][ks][0], qa[1][ks][1], qa[1][ks][2], qa[1][ks][3], r0, r2);
                mma16816(s[1][2 * ntp + 1], qa[1][ks][0], qa[1][ks][1], qa[1][ks][2], qa[1][ks][3], r1, r3);
            }
        }
        if (kc < 64) {
#pragma unroll
            for (int qt = 0; qt < 2; qt++)
#pragma unroll
                for (int nt = 0; nt < 8; nt++) {
                    int c0 = nt * 8 + 2 * t;
                    if (c0 >= kc)     { s[qt][nt][0] = -1e30f; s[qt][nt][2] = -1e30f; }
                    if (c0 + 1 >= kc) { s[qt][nt][1] = -1e30f; s[qt][nt][3] = -1e30f; }
                }
        }
        // online softmax (base-2) per q-tile; pack into pa
        uint32_t pa[2][4][4];
#pragma unroll
        for (int qt = 0; qt < 2; qt++) {
            float mx0 = -1e30f, mx1 = -1e30f;
#pragma unroll
            for (int nt = 0; nt < 8; nt++) {
                mx0 = fmaxf(mx0, fmaxf(s[qt][nt][0], s[qt][nt][1]));
                mx1 = fmaxf(mx1, fmaxf(s[qt][nt][2], s[qt][nt][3]));
            }
            mx0 = qmax(mx0); mx1 = qmax(mx1);
            float mn0 = fmaxf(mrow[qt][0], mx0), mn1 = fmaxf(mrow[qt][1], mx1);
            float a0 = ex2(mrow[qt][0] - mn0), a1 = ex2(mrow[qt][1] - mn1);
            mrow[qt][0] = mn0; mrow[qt][1] = mn1;
            float sum0 = 0.f, sum1 = 0.f;
#pragma unroll
            for (int nt = 0; nt < 8; nt++) {
                s[qt][nt][0] = ex2(s[qt][nt][0] - mn0);
                s[qt][nt][1] = ex2(s[qt][nt][1] - mn0);
                s[qt][nt][2] = ex2(s[qt][nt][2] - mn1);
                s[qt][nt][3] = ex2(s[qt][nt][3] - mn1);
                sum0 += s[qt][nt][0] + s[qt][nt][1];
                sum1 += s[qt][nt][2] + s[qt][nt][3];
            }
            sum0 = qsum(sum0); sum1 = qsum(sum1);
            lrow[qt][0] = lrow[qt][0] * a0 + sum0;
            lrow[qt][1] = lrow[qt][1] * a1 + sum1;
#pragma unroll
            for (int j = 0; j < 4; j++) {
                pa[qt][j][0] = pack2(s[qt][2 * j][0],     s[qt][2 * j][1]);
                pa[qt][j][1] = pack2(s[qt][2 * j][2],     s[qt][2 * j][3]);
                pa[qt][j][2] = pack2(s[qt][2 * j + 1][0], s[qt][2 * j + 1][1]);
                pa[qt][j][3] = pack2(s[qt][2 * j + 1][2], s[qt][2 * j + 1][3]);
            }
            // rescale O
#pragma unroll
            for (int nt = 0; nt < 8; nt++) {
                o[qt][nt][0] *= a0; o[qt][nt][1] *= a0;
                o[qt][nt][2] *= a1; o[qt][nt][3] *= a1;
            }
        }
        // O += P @ V for BOTH q-tiles; each V frag feeds 4 mmas
#pragma unroll
        for (int j = 0; j < 4; j++) {
#pragma unroll
            for (int dg = 0; dg < 4; dg++) {
                uint32_t v0, v1, v2, v3;
                ldsm4t(v0, v1, v2, v3, vbase + j * 16 * 144 + dg * 32);
                mma16816(o[0][2 * dg],     pa[0][j][0], pa[0][j][1], pa[0][j][2], pa[0][j][3], v0, v1);
                mma16816(o[0][2 * dg + 1], pa[0][j][0], pa[0][j][1], pa[0][j][2], pa[0][j][3], v2, v3);
                mma16816(o[1][2 * dg],     pa[1][j][0], pa[1][j][1], pa[1][j][2], pa[1][j][3], v0, v1);
                mma16816(o[1][2 * dg + 1], pa[1][j][0], pa[1][j][1], pa[1][j][2], pa[1][j][3], v2, v3);
            }
        }
    }

    // normalize + store both q-tiles to AO [b*N+n][h*64+d] (fp16)
#pragma unroll
    for (int qt = 0; qt < 2; qt++) {
        float inv0 = 1.f / lrow[qt][0], inv1 = 1.f / lrow[qt][1];
        size_t ro0 = ((size_t)b * Nq + (m0 + qt * 16 + g)) * Cc + h * 64;
        size_t ro1 = ro0 + (size_t)8 * Cc;
#pragma unroll
        for (int nt = 0; nt < 8; nt++) {
            int c = nt * 8 + 2 * t;
            *(__half2*)(g_AO + ro0 + c) = __floats2half2_rn(o[qt][nt][0] * inv0, o[qt][nt][1] * inv0);
            *(__half2*)(g_AO + ro1 + c) = __floats2half2_rn(o[qt][nt][2] * inv1, o[qt][nt][3] * inv1);
        }
    }
}

// ---------------- launch ----------------
extern "C" void kernel_launch(void* const* d_in, const int* in_sizes, int n_in,
                              void* d_out, int out_size) {
    const float* x  = (const float*)d_in[0];
    const float* pk = (const float*)d_in[1];
    const float* pv = (const float*)d_in[2];
    const float* wq = (const float*)d_in[3];
    const float* wp = (const float*)d_in[4];
    const float* bp = (const float*)d_in[5];
    float* out = (float*)d_out;

    (void)in_sizes; (void)n_in; (void)out_size;

    static bool attr_set = false;
    if (!attr_set) {
        cudaFuncSetAttribute(gemm_kernel<0>, cudaFuncAttributeMaxDynamicSharedMemorySize, GSMEM_BYTES);
        cudaFuncSetAttribute(gemm_kernel<1>, cudaFuncAttributeMaxDynamicSharedMemorySize, GSMEM_BYTES);
        cudaFuncSetAttribute(flash_kernel,   cudaFuncAttributeMaxDynamicSharedMemorySize, FSMEM_BYTES);
        attr_set = true;
    }

    int totq = NX4 + NQ4 + NP4;
    convert_all<<<(totq + 255) / 256, 256>>>(x, wq, wp);
    prefix_kernel<<<(Bb * Pp * Cc + 255) / 256, 256>>>(pk, pv);
    {
        dim3 grid(3 * Cc / 128, Mr / 128);        // (24, 128), 128 thr
        gemm_kernel<0><<<grid, 128, GSMEM_BYTES>>>(nullptr, nullptr);
    }
    {
        dim3 grid(Nq / 128, Bb * Hh);             // (8, 256), 128 thr
        flash_kernel<<<grid, 128, FSMEM_BYTES>>>();
    }
    {
        dim3 grid(Cc / 128, Mr / 128);            // (8, 128), 128 thr
        gemm_kernel<1><<<grid, 128, GSMEM_BYTES>>>(out, bp);
    }
}